// round 2
// baseline (speedup 1.0000x reference)
#include <cuda_runtime.h>
#include <cuda_fp16.h>
#include <cstdint>

#define NSTEPS   64
#define NTHREADS 256
#define NTILES   2048            // 262144 rows / 128 per CTA

// SMEM layout (dynamic): W1 as [256 rows][64 k] half, rows padded to 72 halves (144B)
//                        W2 as [64 rows][256 k] half, rows padded to 264 halves (528B)
#define OFF_W1 0u                // 256*144 = 36864
#define OFF_W2 36864u            // 64*528  = 33792
#define OFF_B1 70656u            // 256 f32 = 1024
#define SMEM_BYTES 71680u

static __device__ __forceinline__ uint32_t smem_u32(const void* p) {
    uint32_t a;
    asm("{ .reg .u64 t; cvta.to.shared.u64 t, %1; cvt.u32.u64 %0, t; }" : "=r"(a) : "l"(p));
    return a;
}

static __device__ __forceinline__ void ldsm4(uint32_t* r, uint32_t addr) {
    asm volatile("ldmatrix.sync.aligned.m8n8.x4.shared.b16 {%0,%1,%2,%3}, [%4];"
                 : "=r"(r[0]), "=r"(r[1]), "=r"(r[2]), "=r"(r[3]) : "r"(addr));
}

// D += A(16x16) * B(16x8), f16 inputs, f32 accum
static __device__ __forceinline__ void mma16816(float* d, const uint32_t* a,
                                                uint32_t b0, uint32_t b1) {
    asm volatile(
        "mma.sync.aligned.m16n8k16.row.col.f32.f16.f16.f32 "
        "{%0,%1,%2,%3}, {%4,%5,%6,%7}, {%8,%9}, {%0,%1,%2,%3};"
        : "+f"(d[0]), "+f"(d[1]), "+f"(d[2]), "+f"(d[3])
        : "r"(a[0]), "r"(a[1]), "r"(a[2]), "r"(a[3]), "r"(b0), "r"(b1));
}

static __device__ __forceinline__ uint32_t pack_h2(float a, float b) {
    __half2 h = __floats2half2_rn(a, b);
    return *reinterpret_cast<const uint32_t*>(&h);
}
static __device__ __forceinline__ float elu_f(float x) {
    return x > 0.0f ? x : (__expf(x) - 1.0f);
}

__global__ void __launch_bounds__(NTHREADS, 1)
node_rk4_kernel(const float* __restrict__ x, const float* __restrict__ tptr,
                const float* __restrict__ W1, const float* __restrict__ b1,
                const float* __restrict__ W2, const float* __restrict__ b2,
                float* __restrict__ out)
{
    extern __shared__ char base[];
    const int tid = threadIdx.x;
    const int wid = tid >> 5;
    const int lid = tid & 31;
    const int g   = lid >> 2;    // groupID (row within tile)
    const int tig = lid & 3;     // thread-in-group (column pair)

    // ---- Phase A: stage x tile into SMEM (reuses W1 region), pull y into regs ----
    {
        const float4* xin = reinterpret_cast<const float4*>(x + (size_t)blockIdx.x * (128 * 64));
        float4* stg = reinterpret_cast<float4*>(base);
        for (int i = tid; i < 128 * 64 / 4; i += NTHREADS) stg[i] = xin[i];
    }
    __syncthreads();

    // y in mma C-layout: y[4t+{0,1}] = (row g,   cols 8t+2*tig+{0,1})
    //                    y[4t+{2,3}] = (row g+8, same cols)
    float y[32];
    {
        const float2* xs2 = reinterpret_cast<const float2*>(base);
        const int r0 = wid * 16 + g, r1 = r0 + 8;
        #pragma unroll
        for (int t = 0; t < 8; t++) {
            float2 v0 = xs2[r0 * 32 + 4 * t + tig];
            float2 v1 = xs2[r1 * 32 + 4 * t + tig];
            y[4*t+0] = v0.x; y[4*t+1] = v0.y; y[4*t+2] = v1.x; y[4*t+3] = v1.y;
        }
    }
    __syncthreads();

    // ---- Phase B: stage weights (fp16) + b1 (f32) into SMEM ----
    for (int i = tid; i < 256 * 64; i += NTHREADS) {
        int n = i >> 6, k = i & 63;
        *reinterpret_cast<__half*>(base + OFF_W1 + n * 144 + k * 2) = __float2half_rn(W1[i]);
    }
    for (int i = tid; i < 64 * 256; i += NTHREADS) {
        int n = i >> 8, k = i & 255;
        *reinterpret_cast<__half*>(base + OFF_W2 + n * 528 + k * 2) = __float2half_rn(W2[i]);
    }
    for (int i = tid; i < 256; i += NTHREADS)
        reinterpret_cast<float*>(base + OFF_B1)[i] = b1[i];
    __syncthreads();

    // b2 column-pairs for this thread (D2 C-layout init), from global (L1/L2 cached)
    float b2f[16];
    #pragma unroll
    for (int t = 0; t < 8; t++) {
        float2 v = *reinterpret_cast<const float2*>(b2 + 8 * t + tig * 2);
        b2f[2*t] = v.x; b2f[2*t+1] = v.y;
    }

    const float t0  = tptr[0];
    const float dt  = t0 * (1.0f / (float)NSTEPS);
    const float dt6 = dt * (1.0f / 6.0f);
    const float hdt = 0.5f * dt;

    // ldmatrix per-lane base addresses (tiles: (nlo,klo),(nlo,khi),(nhi,klo),(nhi,khi))
    const uint32_t sb = smem_u32(base);
    const uint32_t lr = lid & 7, lh = (lid >> 3) & 1, ln = (lid >> 4) & 1;
    const uint32_t w1base = sb + OFF_W1 + (lr + 8 * ln) * 144 + lh * 16;
    const uint32_t w2base = sb + OFF_W2 + (lr + 8 * ln) * 528 + lh * 16;
    const float2* b1p = reinterpret_cast<const float2*>(base + OFF_B1);

    uint32_t a1[16];   // A-fragments of GEMM1 ([16,64] f16)
    float acc[32];     // RK4 accumulator, C-layout

    #pragma unroll 1
    for (int step = 0; step < NSTEPS; ++step) {
        #pragma unroll
        for (int j = 0; j < 16; j++) a1[j] = pack_h2(y[2*j], y[2*j+1]);
        #pragma unroll
        for (int j = 0; j < 32; j++) acc[j] = 0.0f;

        #pragma unroll 1
        for (int s = 0; s < 4; s++) {
            // ---- GEMM1: D1[16,256] = A1[16,64] @ W1^T, accum init = b1 ----
            float d1[128];
            #pragma unroll
            for (int t = 0; t < 32; t++) {
                float2 b = b1p[4 * t + tig];
                d1[4*t+0] = b.x; d1[4*t+1] = b.y; d1[4*t+2] = b.x; d1[4*t+3] = b.y;
            }
            #pragma unroll
            for (int ng = 0; ng < 16; ng++) {
                uint32_t bb[16];
                #pragma unroll
                for (int kk = 0; kk < 4; kk++)
                    ldsm4(bb + 4 * kk, w1base + ng * 2304 + kk * 32);
                #pragma unroll
                for (int kk = 0; kk < 4; kk++) {
                    mma16816(d1 + 8 * ng,     a1 + 4 * kk, bb[4*kk+0], bb[4*kk+1]);
                    mma16816(d1 + 8 * ng + 4, a1 + 4 * kk, bb[4*kk+2], bb[4*kk+3]);
                }
            }

            // ---- ELU + pack: C-layout f32 pairs -> A-fragments of GEMM2 ----
            uint32_t a2[64];
            #pragma unroll
            for (int p = 0; p < 64; p++) {
                float v0 = elu_f(d1[2*p+0]);
                float v1 = elu_f(d1[2*p+1]);
                a2[p] = pack_h2(v0, v1);
            }

            // ---- GEMM2: D2[16,64] = A2[16,256] @ W2^T, accum init = b2 ----
            float d2[32];
            #pragma unroll
            for (int t = 0; t < 8; t++) {
                d2[4*t+0] = b2f[2*t]; d2[4*t+1] = b2f[2*t+1];
                d2[4*t+2] = b2f[2*t]; d2[4*t+3] = b2f[2*t+1];
            }
            #pragma unroll
            for (int ng = 0; ng < 4; ng++) {
                #pragma unroll
                for (int kk = 0; kk < 16; kk++) {
                    uint32_t bb[4];
                    ldsm4(bb, w2base + ng * 8448 + kk * 32);
                    mma16816(d2 + 8 * ng,     a2 + 4 * kk, bb[0], bb[1]);
                    mma16816(d2 + 8 * ng + 4, a2 + 4 * kk, bb[2], bb[3]);
                }
            }

            // ---- RK4 stage update (k = d2, biases already included) ----
            const float w  = (s == 1 || s == 2) ? 2.0f : 1.0f;
            const float cn = (s < 2) ? hdt : dt;
            #pragma unroll
            for (int j = 0; j < 32; j++) acc[j] += w * d2[j];
            if (s < 3) {
                #pragma unroll
                for (int j = 0; j < 16; j++)
                    a1[j] = pack_h2(y[2*j] + cn * d2[2*j], y[2*j+1] + cn * d2[2*j+1]);
            }
        }

        #pragma unroll
        for (int j = 0; j < 32; j++) y[j] += dt6 * acc[j];
    }

    // ---- Output (direct STG.64 in C-layout) ----
    {
        float2* o2 = reinterpret_cast<float2*>(out + (size_t)blockIdx.x * (128 * 64));
        const int r0 = wid * 16 + g, r1 = r0 + 8;
        #pragma unroll
        for (int t = 0; t < 8; t++) {
            o2[r0 * 32 + 4 * t + tig] = make_float2(y[4*t+0], y[4*t+1]);
            o2[r1 * 32 + 4 * t + tig] = make_float2(y[4*t+2], y[4*t+3]);
        }
    }
}

extern "C" void kernel_launch(void* const* d_in, const int* in_sizes, int n_in,
                              void* d_out, int out_size) {
    const float* x  = (const float*)d_in[0];
    const float* t  = (const float*)d_in[1];
    const float* W1 = (const float*)d_in[2];
    const float* b1 = (const float*)d_in[3];
    const float* W2 = (const float*)d_in[4];
    const float* b2 = (const float*)d_in[5];
    float* out = (float*)d_out;

    cudaFuncSetAttribute(node_rk4_kernel,
                         cudaFuncAttributeMaxDynamicSharedMemorySize, SMEM_BYTES);
    node_rk4_kernel<<<NTILES, NTHREADS, SMEM_BYTES>>>(x, t, W1, b1, W2, b2, out);
}

// round 3
// speedup vs baseline: 1.4734x; 1.4734x over previous
#include <cuda_runtime.h>
#include <cuda_fp16.h>
#include <cstdint>

#define NSTEPS   64
#define NTHREADS 256
#define NTILES   1024            // 262144 rows / 256 per CTA (M=32 per warp)

// SMEM: W1 [256n][64k] half, rows padded to 144B; W2 [64n][256k] half, rows 528B
//       b1 f32[256]; y state: per-thread 64 f32, rows padded to 272B (bank-clean)
#define OFF_W1 0u                // 36864
#define OFF_W2 36864u            // 33792
#define OFF_B1 70656u            // 1024
#define OFF_Y  71680u            // 256*272 = 69632
#define YPITCH 272u
#define SMEM_BYTES (OFF_Y + 256u * YPITCH)   // 141312

static __device__ __forceinline__ uint32_t smem_u32(const void* p) {
    uint32_t a;
    asm("{ .reg .u64 t; cvta.to.shared.u64 t, %1; cvt.u32.u64 %0, t; }" : "=r"(a) : "l"(p));
    return a;
}
static __device__ __forceinline__ void ldsm4(uint32_t* r, uint32_t addr) {
    asm volatile("ldmatrix.sync.aligned.m8n8.x4.shared.b16 {%0,%1,%2,%3}, [%4];"
                 : "=r"(r[0]), "=r"(r[1]), "=r"(r[2]), "=r"(r[3]) : "r"(addr));
}
static __device__ __forceinline__ void mma16816(float* d, const uint32_t* a,
                                                uint32_t b0, uint32_t b1) {
    asm volatile(
        "mma.sync.aligned.m16n8k16.row.col.f32.f16.f16.f32 "
        "{%0,%1,%2,%3}, {%4,%5,%6,%7}, {%8,%9}, {%0,%1,%2,%3};"
        : "+f"(d[0]), "+f"(d[1]), "+f"(d[2]), "+f"(d[3])
        : "r"(a[0]), "r"(a[1]), "r"(a[2]), "r"(a[3]), "r"(b0), "r"(b1));
}
static __device__ __forceinline__ uint32_t pack_h2(float a, float b) {
    __half2 h = __floats2half2_rn(a, b);
    return *reinterpret_cast<const uint32_t*>(&h);
}
static __device__ __forceinline__ __half2 exp2h2(__half2 v) {
    uint32_t r, x = *reinterpret_cast<const uint32_t*>(&v);
    asm("ex2.approx.f16x2 %0, %1;" : "=r"(r) : "r"(x));
    return *reinterpret_cast<const __half2*>(&r);
}
// branchless fp16x2 ELU: max(x,0) + (exp(min(x,0)) - 1)
static __device__ __forceinline__ uint32_t elu2(float v0, float v1) {
    const __half2 z    = __float2half2_rn(0.0f);
    const __half2 l2e  = __float2half2_rn(1.44269504f);
    const __half2 one  = __float2half2_rn(1.0f);
    __half2 h  = __floats2half2_rn(v0, v1);
    __half2 mn = __hmin2(h, z);
    __half2 mx = __hmax2(h, z);
    __half2 e  = exp2h2(__hmul2(mn, l2e));
    __half2 r  = __hadd2(mx, __hsub2(e, one));
    return *reinterpret_cast<const uint32_t*>(&r);
}

__global__ void __launch_bounds__(NTHREADS, 1)
node_rk4_kernel(const float* __restrict__ x, const float* __restrict__ tptr,
                const float* __restrict__ W1, const float* __restrict__ b1,
                const float* __restrict__ W2, const float* __restrict__ b2,
                float* __restrict__ out)
{
    extern __shared__ char base[];
    const int tid = threadIdx.x;
    const int wid = tid >> 5;
    const int lid = tid & 31;
    const int g   = lid >> 2;
    const int tig = lid & 3;

    // ---- stage weights (fp16, padded rows) + b1 ----
    for (int i = tid; i < 256 * 64; i += NTHREADS) {
        int n = i >> 6, k = i & 63;
        *reinterpret_cast<__half*>(base + OFF_W1 + n * 144 + k * 2) = __float2half_rn(W1[i]);
    }
    for (int i = tid; i < 64 * 256; i += NTHREADS) {
        int n = i >> 8, k = i & 255;
        *reinterpret_cast<__half*>(base + OFF_W2 + n * 528 + k * 2) = __float2half_rn(W2[i]);
    }
    for (int i = tid; i < 256; i += NTHREADS)
        reinterpret_cast<float*>(base + OFF_B1)[i] = b1[i];

    const uint32_t sb = smem_u32(base);
    const uint32_t lr = lid & 7, lh = (lid >> 3) & 1, ln = (lid >> 4) & 1;
    const uint32_t w1base = sb + OFF_W1 + (lr + 8 * ln) * 144 + lh * 16;
    const uint32_t w2base = sb + OFF_W2 + (lr + 8 * ln) * 528 + lh * 16;
    const float2* b1p = reinterpret_cast<const float2*>(base + OFF_B1);
    float* yp = reinterpret_cast<float*>(base + OFF_Y + (uint32_t)tid * YPITCH);

    // b2 pairs for this thread's columns (same for all row tiles)
    float b2f[16];
    #pragma unroll
    for (int t = 0; t < 8; t++) {
        float2 v = *reinterpret_cast<const float2*>(b2 + 8 * t + tig * 2);
        b2f[2*t] = v.x; b2f[2*t+1] = v.y;
    }

    const float t0f = tptr[0];
    const float dt  = t0f * (1.0f / (float)NSTEPS);
    const float dt6 = dt * (1.0f / 6.0f);
    const float hdt = 0.5f * dt;

    // ---- initial y: gather C-layout slices from global x ----
    const int rowbase = blockIdx.x * 256 + wid * 32 + g;
    uint32_t a1[32];                      // A-frags of GEMM1, 2 rowsets x 16
    {
        float yl[64];
        #pragma unroll
        for (int rs = 0; rs < 2; rs++)
            #pragma unroll
            for (int h = 0; h < 2; h++) {
                const float2* src = reinterpret_cast<const float2*>(
                    x + (size_t)(rowbase + rs * 16 + h * 8) * 64);
                #pragma unroll
                for (int t = 0; t < 8; t++) {
                    float2 v = src[4 * t + tig];
                    yl[rs*32 + 4*t + 2*h]     = v.x;
                    yl[rs*32 + 4*t + 2*h + 1] = v.y;
                }
            }
        #pragma unroll
        for (int q = 0; q < 16; q++) {
            float4 v = make_float4(yl[4*q], yl[4*q+1], yl[4*q+2], yl[4*q+3]);
            reinterpret_cast<float4*>(yp)[q] = v;
        }
        #pragma unroll
        for (int rs = 0; rs < 2; rs++)
            #pragma unroll
            for (int j = 0; j < 16; j++)
                a1[rs*16 + j] = pack_h2(yl[rs*32 + 2*j], yl[rs*32 + 2*j + 1]);
    }
    __syncthreads();

    // ---- main ODE loop ----
    #pragma unroll 1
    for (int step = 0; step < NSTEPS; ++step) {
        __half2 acc[32];                    // RK4 accumulator (fp16x2), [rs*16+p]
        #pragma unroll
        for (int i = 0; i < 32; i++) acc[i] = __float2half2_rn(0.0f);

        #pragma unroll 1
        for (int s = 0; s < 4; s++) {
            // D2 accumulators (both rowsets), init = b2
            float d2[64];
            #pragma unroll
            for (int rs = 0; rs < 2; rs++)
                #pragma unroll
                for (int t = 0; t < 8; t++) {
                    d2[rs*32 + 4*t + 0] = b2f[2*t];
                    d2[rs*32 + 4*t + 1] = b2f[2*t+1];
                    d2[rs*32 + 4*t + 2] = b2f[2*t];
                    d2[rs*32 + 4*t + 3] = b2f[2*t+1];
                }

            // loop over hidden chunks of 64
            #pragma unroll 1
            for (int hc = 0; hc < 4; hc++) {
                float d1c[64];              // [rs*32 + 8*ngl + q], init = b1 chunk
                #pragma unroll
                for (int ngl = 0; ngl < 4; ngl++) {
                    int t0 = 8 * hc + 2 * ngl;   // n8-tile index
                    float2 bA = b1p[4*t0 + tig];
                    float2 bB = b1p[4*t0 + 4 + tig];
                    #pragma unroll
                    for (int rs = 0; rs < 2; rs++) {
                        d1c[rs*32 + 8*ngl + 0] = bA.x; d1c[rs*32 + 8*ngl + 1] = bA.y;
                        d1c[rs*32 + 8*ngl + 2] = bA.x; d1c[rs*32 + 8*ngl + 3] = bA.y;
                        d1c[rs*32 + 8*ngl + 4] = bB.x; d1c[rs*32 + 8*ngl + 5] = bB.y;
                        d1c[rs*32 + 8*ngl + 6] = bB.x; d1c[rs*32 + 8*ngl + 7] = bB.y;
                    }
                }
                // GEMM1 chunk: reuse each B-frag for both rowsets
                #pragma unroll
                for (int ngl = 0; ngl < 4; ngl++) {
                    #pragma unroll
                    for (int kk = 0; kk < 4; kk++) {
                        uint32_t bb[4];
                        ldsm4(bb, w1base + (uint32_t)(4*hc + ngl) * 2304 + kk * 32);
                        mma16816(d1c + 8*ngl,          a1 + 4*kk,      bb[0], bb[1]);
                        mma16816(d1c + 8*ngl + 4,      a1 + 4*kk,      bb[2], bb[3]);
                        mma16816(d1c + 32 + 8*ngl,     a1 + 16 + 4*kk, bb[0], bb[1]);
                        mma16816(d1c + 32 + 8*ngl + 4, a1 + 16 + 4*kk, bb[2], bb[3]);
                    }
                }
                // ELU -> fp16 A-frags of GEMM2 (chunk-local k64)
                uint32_t a2c[32];
                #pragma unroll
                for (int rs = 0; rs < 2; rs++)
                    #pragma unroll
                    for (int p = 0; p < 16; p++)
                        a2c[rs*16 + p] = elu2(d1c[rs*32 + 2*p], d1c[rs*32 + 2*p + 1]);
                // GEMM2 partial over this k64 chunk
                #pragma unroll
                for (int ng2 = 0; ng2 < 4; ng2++) {
                    #pragma unroll
                    for (int kk2 = 0; kk2 < 4; kk2++) {
                        uint32_t bb[4];
                        ldsm4(bb, w2base + (uint32_t)ng2 * 8448 + (uint32_t)(4*hc + kk2) * 32);
                        mma16816(d2 + 8*ng2,          a2c + 4*kk2,      bb[0], bb[1]);
                        mma16816(d2 + 8*ng2 + 4,      a2c + 4*kk2,      bb[2], bb[3]);
                        mma16816(d2 + 32 + 8*ng2,     a2c + 16 + 4*kk2, bb[0], bb[1]);
                        mma16816(d2 + 32 + 8*ng2 + 4, a2c + 16 + 4*kk2, bb[2], bb[3]);
                    }
                }
            }

            // ---- RK4 stage update ----
            const __half2 wh = __float2half2_rn((s == 1 || s == 2) ? 2.0f : 1.0f);
            #pragma unroll
            for (int i = 0; i < 32; i++) {
                __half2 pk = __floats2half2_rn(d2[2*i], d2[2*i+1]);
                acc[i] = __hfma2(pk, wh, acc[i]);
            }
            float yl[64];
            #pragma unroll
            for (int q = 0; q < 16; q++) {
                float4 v = reinterpret_cast<const float4*>(yp)[q];
                yl[4*q] = v.x; yl[4*q+1] = v.y; yl[4*q+2] = v.z; yl[4*q+3] = v.w;
            }
            if (s < 3) {
                const float cn = (s < 2) ? hdt : dt;
                #pragma unroll
                for (int rs = 0; rs < 2; rs++)
                    #pragma unroll
                    for (int j = 0; j < 16; j++)
                        a1[rs*16 + j] = pack_h2(yl[rs*32 + 2*j]     + cn * d2[rs*32 + 2*j],
                                                yl[rs*32 + 2*j + 1] + cn * d2[rs*32 + 2*j + 1]);
            } else {
                #pragma unroll
                for (int i = 0; i < 32; i++) {
                    float2 af = __half22float2(acc[i]);
                    yl[2*i]     += dt6 * af.x;
                    yl[2*i + 1] += dt6 * af.y;
                }
                #pragma unroll
                for (int q = 0; q < 16; q++) {
                    float4 v = make_float4(yl[4*q], yl[4*q+1], yl[4*q+2], yl[4*q+3]);
                    reinterpret_cast<float4*>(yp)[q] = v;
                }
                #pragma unroll
                for (int rs = 0; rs < 2; rs++)
                    #pragma unroll
                    for (int j = 0; j < 16; j++)
                        a1[rs*16 + j] = pack_h2(yl[rs*32 + 2*j], yl[rs*32 + 2*j + 1]);
            }
        }
    }

    // ---- output ----
    {
        float yl[64];
        #pragma unroll
        for (int q = 0; q < 16; q++) {
            float4 v = reinterpret_cast<const float4*>(yp)[q];
            yl[4*q] = v.x; yl[4*q+1] = v.y; yl[4*q+2] = v.z; yl[4*q+3] = v.w;
        }
        #pragma unroll
        for (int rs = 0; rs < 2; rs++)
            #pragma unroll
            for (int h = 0; h < 2; h++) {
                float2* dst = reinterpret_cast<float2*>(
                    out + (size_t)(rowbase + rs * 16 + h * 8) * 64);
                #pragma unroll
                for (int t = 0; t < 8; t++)
                    dst[4 * t + tig] = make_float2(yl[rs*32 + 4*t + 2*h],
                                                   yl[rs*32 + 4*t + 2*h + 1]);
            }
    }
}

extern "C" void kernel_launch(void* const* d_in, const int* in_sizes, int n_in,
                              void* d_out, int out_size) {
    const float* x  = (const float*)d_in[0];
    const float* t  = (const float*)d_in[1];
    const float* W1 = (const float*)d_in[2];
    const float* b1 = (const float*)d_in[3];
    const float* W2 = (const float*)d_in[4];
    const float* b2 = (const float*)d_in[5];
    float* out = (float*)d_out;

    cudaFuncSetAttribute(node_rk4_kernel,
                         cudaFuncAttributeMaxDynamicSharedMemorySize, SMEM_BYTES);
    node_rk4_kernel<<<NTILES, NTHREADS, SMEM_BYTES>>>(x, t, W1, b1, W2, b2, out);
}